// round 8
// baseline (speedup 1.0000x reference)
#include <cuda_runtime.h>
#include <cuda_fp16.h>

#define TAB 2048
#define FULLMASK 0xffffffffu
typedef unsigned long long ull;

__device__ __half g_htabh[2][TAB * 128];   // 1 MB total: length->h tables, fp16

// fast silu: x*sigmoid(x) = h*tanh(h)+h with h=x/2  (1 MUFU)
__device__ __forceinline__ float silu_f(float x) {
    float h = 0.5f * x, t;
    asm("tanh.approx.f32 %0, %1;" : "=f"(t) : "f"(h));
    return fmaf(h, t, h);
}
// accurate silu for one-time table build
__device__ __forceinline__ float silu_acc(float x) { return __fdividef(x, 1.0f + __expf(-x)); }

__device__ __forceinline__ ull dup2(float x) {
    ull r; unsigned u = __float_as_uint(x);
    asm("mov.b64 %0, {%1,%1};" : "=l"(r) : "r"(u)); return r;
}
__device__ __forceinline__ ull pack2(float a, float b) {
    ull r;
    asm("mov.b64 %0, {%1,%2};" : "=l"(r) : "r"(__float_as_uint(a)), "r"(__float_as_uint(b)));
    return r;
}
__device__ __forceinline__ void fma2(ull &d, ull a, ull b) {
    asm("fma.rn.f32x2 %0, %1, %2, %0;" : "+l"(d) : "l"(a), "l"(b));
}
__device__ __forceinline__ void unpack2(ull v, float &lo, float &hi) {
    unsigned a, b; asm("mov.b64 {%0,%1}, %2;" : "=r"(a), "=r"(b) : "l"(v));
    lo = __uint_as_float(a); hi = __uint_as_float(b);
}

// ---------------------------------------------------------------------------
// Length -> h(128) table builder (fp16 output). Thread f owns feature f.
// ---------------------------------------------------------------------------
__global__ void __launch_bounds__(128) build_tab_kernel(
    const float* __restrict__ w1a, const float* __restrict__ b1a,
    const float* __restrict__ w2a, const float* __restrict__ b2a,
    const float* __restrict__ w1b, const float* __restrict__ b1b,
    const float* __restrict__ w2b, const float* __restrict__ b2b,
    int rows_per_block)
{
    int filt = blockIdx.y;
    const float* w1 = filt ? w1b : w1a; const float* b1 = filt ? b1b : b1a;
    const float* w2 = filt ? w2b : w2a; const float* b2 = filt ? b2b : b2a;
    __shared__ float h1s[128];
    int f = threadIdx.x;
    float wcol[128], w1col[32];
#pragma unroll
    for (int k = 0; k < 128; k++) wcol[k] = __ldg(&w2[k * 128 + f]);
#pragma unroll
    for (int k = 0; k < 32; k++) w1col[k] = __ldg(&w1[k * 128 + f]);
    float b1f = __ldg(&b1[f]), b2f = __ldg(&b2[f]);
    const float step  = 5.0f / 31.0f;
    const float gamma = 0.5f / (step * step);
    const float dx    = 5.0f / (float)(TAB - 1);
    int r0 = blockIdx.x * rows_per_block;
    for (int rr = 0; rr < rows_per_block; rr++) {
        int row = r0 + rr;
        float x = (float)row * dx;
        float a1 = b1f;
#pragma unroll
        for (int k = 0; k < 32; k++) {
            float d = x - (float)k * step;
            a1 = fmaf(__expf(-gamma * d * d), w1col[k], a1);
        }
        h1s[f] = silu_acc(a1);
        __syncthreads();
        float a2 = b2f;
#pragma unroll
        for (int k = 0; k < 128; k++) a2 = fmaf(h1s[k], wcol[k], a2);
        g_htabh[filt][(size_t)row * 128 + f] = __float2half_rn(silu_acc(a2));
        __syncthreads();
    }
}

// ---------------------------------------------------------------------------
// Node kernel: 8 nodes per warp, f32x2 node-pairs.
// t = [2*inv | so3(2*ev)] @ w_int + b_int
// out1 = 2*inv + t[:,:128]; out2 = 2*ev * (1 + t[:,128:][seg]).
// ---------------------------------------------------------------------------
__global__ void __launch_bounds__(256) node_kernel(
    const float* __restrict__ invf, const float* __restrict__ evf,
    const float* __restrict__ w_int, const float* __restrict__ b_int,
    float* __restrict__ out1, float* __restrict__ out2, int N)
{
    __shared__ float2 xs[8][4][136];   // [warp][node-pair][feature] (x=even node, y=odd)
    int warp = threadIdx.x >> 5, lane = threadIdx.x & 31;
    int ngrp = (N + 7) >> 3;
    int grp = blockIdx.x * 8 + warp;
    if (grp >= ngrp) return;
    int nbase = grp * 8;
    int o4 = (lane < 4) ? (128 + lane) : lane;

    float attv[8];
#pragma unroll
    for (int nd = 0; nd < 8; nd++) {
        int n = nbase + nd; if (n >= N) n = N - 1;
        float* Xp = reinterpret_cast<float*>(xs[warp][nd >> 1]) + (nd & 1);
#pragma unroll
        for (int j = 0; j < 4; j++)
            Xp[2 * (lane + 32 * j)] = 2.0f * __ldg(invf + (size_t)n * 128 + lane + 32 * j);
        float av = 0.f, dsq = 0.f;
        if (lane < 16) { av = 2.0f * __ldg(evf + (size_t)n * 16 + lane); dsq = av * av; }
        attv[nd] = av;
        float v0 = __shfl_sync(FULLMASK, dsq, 0);
        float v1 = __shfl_sync(FULLMASK, dsq, 1) + __shfl_sync(FULLMASK, dsq, 2)
                 + __shfl_sync(FULLMASK, dsq, 3);
        float v2 = __shfl_sync(FULLMASK, dsq, 4) + __shfl_sync(FULLMASK, dsq, 5)
                 + __shfl_sync(FULLMASK, dsq, 6) + __shfl_sync(FULLMASK, dsq, 7)
                 + __shfl_sync(FULLMASK, dsq, 8);
        float v3 = __shfl_sync(FULLMASK, dsq, 9) + __shfl_sync(FULLMASK, dsq, 10)
                 + __shfl_sync(FULLMASK, dsq, 11) + __shfl_sync(FULLMASK, dsq, 12)
                 + __shfl_sync(FULLMASK, dsq, 13) + __shfl_sync(FULLMASK, dsq, 14)
                 + __shfl_sync(FULLMASK, dsq, 15);
        if (lane == 0) { Xp[2*128] = v0; Xp[2*129] = v1; Xp[2*130] = v2; Xp[2*131] = v3; }
    }
    __syncwarp();

    ull acc[4][5];
    {
        ull d0 = dup2(__ldg(b_int + lane)),      d1 = dup2(__ldg(b_int + 32 + lane));
        ull d2 = dup2(__ldg(b_int + 64 + lane)), d3 = dup2(__ldg(b_int + 96 + lane));
        ull d4 = dup2(__ldg(b_int + o4));
#pragma unroll
        for (int p = 0; p < 4; p++) {
            acc[p][0] = d0; acc[p][1] = d1; acc[p][2] = d2; acc[p][3] = d3; acc[p][4] = d4;
        }
    }
#pragma unroll 2
    for (int i = 0; i < 132; i++) {
        const float* wr = w_int + i * 132;
        ull w0 = dup2(__ldg(wr + lane)),      w1 = dup2(__ldg(wr + 32 + lane));
        ull w2 = dup2(__ldg(wr + 64 + lane)), w3 = dup2(__ldg(wr + 96 + lane));
        ull w4 = dup2(__ldg(wr + o4));
#pragma unroll
        for (int p = 0; p < 4; p++) {
            ull x = reinterpret_cast<const ull*>(xs[warp][p])[i];
            fma2(acc[p][0], w0, x); fma2(acc[p][1], w1, x);
            fma2(acc[p][2], w2, x); fma2(acc[p][3], w3, x);
            fma2(acc[p][4], w4, x);
        }
    }
#pragma unroll
    for (int nd = 0; nd < 8; nd++) {
        int n = nbase + nd;
        if (n >= N) break;
        int p = nd >> 1, s = nd & 1;
        const float* Xp = reinterpret_cast<const float*>(xs[warp][p]) + s;
        float lo, hi, a0, a1, a2, a3, a4;
        unpack2(acc[p][0], lo, hi); a0 = s ? hi : lo;
        unpack2(acc[p][1], lo, hi); a1 = s ? hi : lo;
        unpack2(acc[p][2], lo, hi); a2 = s ? hi : lo;
        unpack2(acc[p][3], lo, hi); a3 = s ? hi : lo;
        unpack2(acc[p][4], lo, hi); a4 = s ? hi : lo;
        out1[(size_t)n * 128 + lane]      = Xp[2 * (lane)]      + a0;
        out1[(size_t)n * 128 + 32 + lane] = Xp[2 * (32 + lane)] + a1;
        out1[(size_t)n * 128 + 64 + lane] = Xp[2 * (64 + lane)] + a2;
        out1[(size_t)n * 128 + 96 + lane] = Xp[2 * (96 + lane)] + a3;
        float c0 = __shfl_sync(FULLMASK, a4, 0), c1 = __shfl_sync(FULLMASK, a4, 1);
        float c2 = __shfl_sync(FULLMASK, a4, 2), c3 = __shfl_sync(FULLMASK, a4, 3);
        if (lane < 16) {
            float bs = (lane == 0) ? c0 : ((lane < 4) ? c1 : ((lane < 9) ? c2 : c3));
            out2[(size_t)n * 16 + lane] = attv[nd] * (1.0f + bs);
        }
    }
}

// ---------------------------------------------------------------------------
// Edge kernel (merged fi+fe, inline gather, 16 edges per warp pass).
// fw[f] = tab_lerp_fp16[f](length) + silu(silu(inv4 @ w1[f] + b1[f]) @ w2[f] + b2[f])
// ---------------------------------------------------------------------------
__global__ void __launch_bounds__(128) edge_kernel(
    const float* __restrict__ evf, const int* __restrict__ senders,
    const int* __restrict__ receivers, const float* __restrict__ lengths,
    const float* __restrict__ fi_w1, const float* __restrict__ fi_b1,
    const float* __restrict__ fi_w2, const float* __restrict__ fi_b2,
    const float* __restrict__ fe_w1, const float* __restrict__ fe_b1,
    const float* __restrict__ fe_w2, const float* __restrict__ fe_b2,
    float* __restrict__ fwi, float* __restrict__ fwe, int E)
{
    __shared__ __align__(16) float s_w2[2][4096];   // 32 KB
    __shared__ __align__(16) ull   s_e1[4][8][32];  // [warp][edge-pair][k]
    __shared__ __align__(16) float4 s_inv[4][16];
    __shared__ float s_tf[4][16];
    __shared__ int   s_ti[4][16];

    int tid = threadIdx.x;
    for (int i = tid; i < 4096; i += 128) { s_w2[0][i] = fi_w2[i]; s_w2[1][i] = fe_w2[i]; }
    __syncthreads();

    int warp = tid >> 5, lane = tid & 31;
    float w1l[2][4], bl[2]; float4 bb[2];
    w1l[0][0] = __ldg(fi_w1 + lane);      w1l[0][1] = __ldg(fi_w1 + 32 + lane);
    w1l[0][2] = __ldg(fi_w1 + 64 + lane); w1l[0][3] = __ldg(fi_w1 + 96 + lane);
    w1l[1][0] = __ldg(fe_w1 + lane);      w1l[1][1] = __ldg(fe_w1 + 32 + lane);
    w1l[1][2] = __ldg(fe_w1 + 64 + lane); w1l[1][3] = __ldg(fe_w1 + 96 + lane);
    bl[0] = __ldg(fi_b1 + lane); bl[1] = __ldg(fe_b1 + lane);
    bb[0] = __ldg(reinterpret_cast<const float4*>(fi_b2) + lane);
    bb[1] = __ldg(reinterpret_cast<const float4*>(fe_b2) + lane);
    const float tscale = (float)(TAB - 1) / 5.0f;

    int gw = blockIdx.x * 4 + warp;
    int nwarps = gridDim.x * 4;

    for (int base = gw * 16; base < E; base += nwarps * 16) {
        // ---- stage 16 edges: lanes 0-15 = sender nodes, 16-31 = receiver nodes
        {
            int e = base + (lane & 15); if (e >= E) e = E - 1;
            int node = (lane < 16) ? __ldg(senders + e) : __ldg(receivers + e);
            const float4* A = reinterpret_cast<const float4*>(evf) + (size_t)node * 4;
            float4 a0 = __ldg(A), a1 = __ldg(A + 1), a2 = __ldg(A + 2), a3 = __ldg(A + 3);
            a0.x -= __shfl_down_sync(FULLMASK, a0.x, 16);
            a0.y -= __shfl_down_sync(FULLMASK, a0.y, 16);
            a0.z -= __shfl_down_sync(FULLMASK, a0.z, 16);
            a0.w -= __shfl_down_sync(FULLMASK, a0.w, 16);
            a1.x -= __shfl_down_sync(FULLMASK, a1.x, 16);
            a1.y -= __shfl_down_sync(FULLMASK, a1.y, 16);
            a1.z -= __shfl_down_sync(FULLMASK, a1.z, 16);
            a1.w -= __shfl_down_sync(FULLMASK, a1.w, 16);
            a2.x -= __shfl_down_sync(FULLMASK, a2.x, 16);
            a2.y -= __shfl_down_sync(FULLMASK, a2.y, 16);
            a2.z -= __shfl_down_sync(FULLMASK, a2.z, 16);
            a2.w -= __shfl_down_sync(FULLMASK, a2.w, 16);
            a3.x -= __shfl_down_sync(FULLMASK, a3.x, 16);
            a3.y -= __shfl_down_sync(FULLMASK, a3.y, 16);
            a3.z -= __shfl_down_sync(FULLMASK, a3.z, 16);
            a3.w -= __shfl_down_sync(FULLMASK, a3.w, 16);
            if (lane < 16) {
                float i0 = a0.x*a0.x;
                float i1 = a0.y*a0.y + a0.z*a0.z + a0.w*a0.w;
                float i2 = a1.x*a1.x + a1.y*a1.y + a1.z*a1.z + a1.w*a1.w + a2.x*a2.x;
                float i3 = a2.y*a2.y + a2.z*a2.z + a2.w*a2.w
                         + a3.x*a3.x + a3.y*a3.y + a3.z*a3.z + a3.w*a3.w;
                s_inv[warp][lane] = make_float4(i0, i1, i2, i3);
                float xf = __ldg(lengths + e) * tscale;
                int ti = (int)xf;
                if (ti < 0) ti = 0; if (ti > TAB - 2) ti = TAB - 2;
                s_tf[warp][lane] = xf - (float)ti;
                s_ti[warp][lane] = ti;
            }
        }
        __syncwarp();

#pragma unroll 1
        for (int f = 0; f < 2; f++) {
            // layer 1: hidden k = lane, 8 edge-pairs
#pragma unroll
            for (int p = 0; p < 8; p++) {
                float4 v0 = s_inv[warp][2 * p];
                float4 v1 = s_inv[warp][2 * p + 1];
                float ea = silu_f(fmaf(v0.x, w1l[f][0], fmaf(v0.y, w1l[f][1],
                                  fmaf(v0.z, w1l[f][2], fmaf(v0.w, w1l[f][3], bl[f])))));
                float eb = silu_f(fmaf(v1.x, w1l[f][0], fmaf(v1.y, w1l[f][1],
                                  fmaf(v1.z, w1l[f][2], fmaf(v1.w, w1l[f][3], bl[f])))));
                s_e1[warp][p][lane] = pack2(ea, eb);
            }
            __syncwarp();

            // layer 2: 32 -> 128, f32x2 over edge pairs
            ull acc[8][4];
            {
                ull d0 = dup2(bb[f].x), d1 = dup2(bb[f].y), d2 = dup2(bb[f].z), d3 = dup2(bb[f].w);
#pragma unroll
                for (int p = 0; p < 8; p++) { acc[p][0]=d0; acc[p][1]=d1; acc[p][2]=d2; acc[p][3]=d3; }
            }
            const float4* wv = reinterpret_cast<const float4*>(s_w2[f]);
#pragma unroll 2
            for (int k2 = 0; k2 < 16; k2++) {
                float4 wa = wv[(2 * k2) * 32 + lane];
                float4 wb = wv[(2 * k2 + 1) * 32 + lane];
                ull wa0 = dup2(wa.x), wa1 = dup2(wa.y), wa2 = dup2(wa.z), wa3 = dup2(wa.w);
                ull wb0 = dup2(wb.x), wb1 = dup2(wb.y), wb2 = dup2(wb.z), wb3 = dup2(wb.w);
#pragma unroll
                for (int p = 0; p < 8; p++) {
                    float4 cc = reinterpret_cast<const float4*>(s_e1[warp][p])[k2];
                    ull c0 = pack2(cc.x, cc.y);
                    ull c1 = pack2(cc.z, cc.w);
                    fma2(acc[p][0], wa0, c0); fma2(acc[p][1], wa1, c0);
                    fma2(acc[p][2], wa2, c0); fma2(acc[p][3], wa3, c0);
                    fma2(acc[p][0], wb0, c1); fma2(acc[p][1], wb1, c1);
                    fma2(acc[p][2], wb2, c1); fma2(acc[p][3], wb3, c1);
                }
            }

            // epilogue: silu + fp16 table lerp + store
            float4* outv = reinterpret_cast<float4*>(f ? fwe : fwi);
            const __half* tabh = g_htabh[f];
#pragma unroll
            for (int p = 0; p < 8; p++) {
                float l0, h0, l1, h1, l2, h2, l3, h3;
                unpack2(acc[p][0], l0, h0); unpack2(acc[p][1], l1, h1);
                unpack2(acc[p][2], l2, h2); unpack2(acc[p][3], l3, h3);
#pragma unroll
                for (int hh = 0; hh < 2; hh++) {
                    int j = 2 * p + hh;
                    int e = base + j;
                    if (e < E) {
                        float e0 = hh ? h0 : l0, e1 = hh ? h1 : l1;
                        float e2 = hh ? h2 : l2, e3 = hh ? h3 : l3;
                        float tf = s_tf[warp][j];
                        int   ti = s_ti[warp][j];
                        const uint2* ta = reinterpret_cast<const uint2*>(tabh + (size_t)ti * 128) + lane;
                        uint2 ua = __ldg(ta);
                        uint2 ub = __ldg(ta + 32);
                        float2 a01 = __half22float2(*reinterpret_cast<__half2*>(&ua.x));
                        float2 a23 = __half22float2(*reinterpret_cast<__half2*>(&ua.y));
                        float2 b01 = __half22float2(*reinterpret_cast<__half2*>(&ub.x));
                        float2 b23 = __half22float2(*reinterpret_cast<__half2*>(&ub.y));
                        float4 o;
                        o.x = fmaf(tf, b01.x - a01.x, a01.x) + silu_f(e0);
                        o.y = fmaf(tf, b01.y - a01.y, a01.y) + silu_f(e1);
                        o.z = fmaf(tf, b23.x - a23.x, a23.x) + silu_f(e2);
                        o.w = fmaf(tf, b23.y - a23.y, a23.y) + silu_f(e3);
                        outv[(size_t)e * 32 + lane] = o;
                    }
                }
            }
            __syncwarp();
        }
    }
}

// ---------------------------------------------------------------------------
extern "C" void kernel_launch(void* const* d_in, const int* in_sizes, int n_in,
                              void* d_out, int out_size)
{
    const float* invf      = (const float*)d_in[0];
    const float* evf       = (const float*)d_in[1];
    const int*   senders   = (const int*)  d_in[2];
    const int*   receivers = (const int*)  d_in[3];
    const float* lengths   = (const float*)d_in[5];
    const float* fi_rbf_w1 = (const float*)d_in[7];
    const float* fi_rbf_b1 = (const float*)d_in[8];
    const float* fi_rbf_w2 = (const float*)d_in[9];
    const float* fi_rbf_b2 = (const float*)d_in[10];
    const float* fi_ev_w1  = (const float*)d_in[11];
    const float* fi_ev_b1  = (const float*)d_in[12];
    const float* fi_ev_w2  = (const float*)d_in[13];
    const float* fi_ev_b2  = (const float*)d_in[14];
    const float* fe_rbf_w1 = (const float*)d_in[15];
    const float* fe_rbf_b1 = (const float*)d_in[16];
    const float* fe_rbf_w2 = (const float*)d_in[17];
    const float* fe_rbf_b2 = (const float*)d_in[18];
    const float* fe_ev_w1  = (const float*)d_in[19];
    const float* fe_ev_b1  = (const float*)d_in[20];
    const float* fe_ev_w2  = (const float*)d_in[21];
    const float* fe_ev_b2  = (const float*)d_in[22];
    const float* w_int     = (const float*)d_in[23];
    const float* b_int     = (const float*)d_in[24];

    int N = in_sizes[0] / 128;
    int E = in_sizes[5];

    float* out1 = (float*)d_out;
    float* out2 = out1 + (size_t)N * 128;
    float* fwi  = out2 + (size_t)N * 16;
    float* fwe  = fwi  + (size_t)E * 128;

    build_tab_kernel<<<dim3(TAB / 32, 2), 128>>>(
        fi_rbf_w1, fi_rbf_b1, fi_rbf_w2, fi_rbf_b2,
        fe_rbf_w1, fe_rbf_b1, fe_rbf_w2, fe_rbf_b2, 32);

    node_kernel<<<(((N + 7) / 8) + 7) / 8, 256>>>(invf, evf, w_int, b_int, out1, out2, N);

    edge_kernel<<<1480, 128>>>(
        evf, senders, receivers, lengths,
        fi_ev_w1, fi_ev_b1, fi_ev_w2, fi_ev_b2,
        fe_ev_w1, fe_ev_b1, fe_ev_w2, fe_ev_b2,
        fwi, fwe, E);
}

// round 9
// speedup vs baseline: 1.3238x; 1.3238x over previous
#include <cuda_runtime.h>
#include <cuda_fp16.h>

#define TAB 2048
#define FULLMASK 0xffffffffu
typedef unsigned long long ull;

__device__ __half g_htabh[2][TAB * 128];   // 1 MB: length->h tables, fp16
__device__ float4 g_einv[1000000];         // per-edge SO3 invariants
__device__ float2 g_etf[1000000];          // per-edge (tf, bitcast ti)

// fast silu: x*sigmoid(x) = h*tanh(h)+h with h=x/2  (1 MUFU)
__device__ __forceinline__ float silu_f(float x) {
    float h = 0.5f * x, t;
    asm("tanh.approx.f32 %0, %1;" : "=f"(t) : "f"(h));
    return fmaf(h, t, h);
}
// accurate silu for one-time table build
__device__ __forceinline__ float silu_acc(float x) { return __fdividef(x, 1.0f + __expf(-x)); }

__device__ __forceinline__ ull dup2(float x) {
    ull r; unsigned u = __float_as_uint(x);
    asm("mov.b64 %0, {%1,%1};" : "=l"(r) : "r"(u)); return r;
}
__device__ __forceinline__ ull pack2(float a, float b) {
    ull r;
    asm("mov.b64 %0, {%1,%2};" : "=l"(r) : "r"(__float_as_uint(a)), "r"(__float_as_uint(b)));
    return r;
}
__device__ __forceinline__ void fma2(ull &d, ull a, ull b) {
    asm("fma.rn.f32x2 %0, %1, %2, %0;" : "+l"(d) : "l"(a), "l"(b));
}
__device__ __forceinline__ void unpack2(ull v, float &lo, float &hi) {
    unsigned a, b; asm("mov.b64 {%0,%1}, %2;" : "=r"(a), "=r"(b) : "l"(v));
    lo = __uint_as_float(a); hi = __uint_as_float(b);
}

// ===========================================================================
// Fused setup kernel: grid sections run concurrently.
//   blocks [0, 128)           : build fp16 length->h tables (2 filters)
//   blocks [128, 128+PB)      : per-edge invariants + table index prep
//   blocks [128+PB, ...)      : node update
// ===========================================================================
__global__ void __launch_bounds__(256) setup_kernel(
    const float* __restrict__ invf, const float* __restrict__ evf,
    const int* __restrict__ senders, const int* __restrict__ receivers,
    const float* __restrict__ lengths,
    const float* __restrict__ fi_rbf_w1, const float* __restrict__ fi_rbf_b1,
    const float* __restrict__ fi_rbf_w2, const float* __restrict__ fi_rbf_b2,
    const float* __restrict__ fe_rbf_w1, const float* __restrict__ fe_rbf_b1,
    const float* __restrict__ fe_rbf_w2, const float* __restrict__ fe_rbf_b2,
    const float* __restrict__ w_int, const float* __restrict__ b_int,
    float* __restrict__ out1, float* __restrict__ out2,
    int N, int E, int PB)
{
    int bid = blockIdx.x;
    int tid = threadIdx.x;

    if (bid < 128) {
        // ---------------- table build: 64 blocks per filter, 32 rows/block ---
        int filt = bid >> 6;
        const float* w1 = filt ? fe_rbf_w1 : fi_rbf_w1;
        const float* b1 = filt ? fe_rbf_b1 : fi_rbf_b1;
        const float* w2 = filt ? fe_rbf_w2 : fi_rbf_w2;
        const float* b2 = filt ? fe_rbf_b2 : fi_rbf_b2;
        __shared__ float h1s[128];
        int f = tid & 127;                  // threads 128-255 duplicate (benign)
        float w1col[32];
#pragma unroll
        for (int k = 0; k < 32; k++) w1col[k] = __ldg(&w1[k * 128 + f]);
        float b1f = __ldg(&b1[f]), b2f = __ldg(&b2[f]);
        const float step  = 5.0f / 31.0f;
        const float gamma = 0.5f / (step * step);
        const float dx    = 5.0f / (float)(TAB - 1);
        int r0 = (bid & 63) * 32;
        for (int rr = 0; rr < 32; rr++) {
            int row = r0 + rr;
            float x = (float)row * dx;
            float a1 = b1f;
#pragma unroll
            for (int k = 0; k < 32; k++) {
                float d = x - (float)k * step;
                a1 = fmaf(__expf(-gamma * d * d), w1col[k], a1);
            }
            h1s[f] = silu_acc(a1);
            __syncthreads();
            float a2 = b2f;
#pragma unroll 16
            for (int k = 0; k < 128; k++) a2 = fmaf(h1s[k], __ldg(&w2[k * 128 + f]), a2);
            g_htabh[filt][(size_t)row * 128 + f] = __float2half_rn(silu_acc(a2));
            __syncthreads();
        }
        return;
    }

    if (bid < 128 + PB) {
        // ---------------- edge prep: one edge per thread ---------------------
        int e = (bid - 128) * 256 + tid;
        if (e >= E) return;
        const float tscale = (float)(TAB - 1) / 5.0f;
        int sN = __ldg(senders + e), rN = __ldg(receivers + e);
        const float4* As = reinterpret_cast<const float4*>(evf) + (size_t)sN * 4;
        const float4* Ar = reinterpret_cast<const float4*>(evf) + (size_t)rN * 4;
        float4 a, b; float dx, dy, dz, dw;
        float i0, i1, i2, i3;
        a = __ldg(As);     b = __ldg(Ar);     dx = a.x-b.x; dy = a.y-b.y; dz = a.z-b.z; dw = a.w-b.w;
        i0 = dx*dx; i1 = dy*dy + dz*dz + dw*dw;
        a = __ldg(As + 1); b = __ldg(Ar + 1); dx = a.x-b.x; dy = a.y-b.y; dz = a.z-b.z; dw = a.w-b.w;
        i2 = dx*dx + dy*dy + dz*dz + dw*dw;
        a = __ldg(As + 2); b = __ldg(Ar + 2); dx = a.x-b.x; dy = a.y-b.y; dz = a.z-b.z; dw = a.w-b.w;
        i2 += dx*dx; i3 = dy*dy + dz*dz + dw*dw;
        a = __ldg(As + 3); b = __ldg(Ar + 3); dx = a.x-b.x; dy = a.y-b.y; dz = a.z-b.z; dw = a.w-b.w;
        i3 += dx*dx + dy*dy + dz*dz + dw*dw;
        float xf = __ldg(lengths + e) * tscale;
        int ti = (int)xf;
        if (ti < 0) ti = 0; if (ti > TAB - 2) ti = TAB - 2;
        g_einv[e] = make_float4(i0, i1, i2, i3);
        g_etf[e]  = make_float2(xf - (float)ti, __int_as_float(ti));
        return;
    }

    // ---------------- node update: 8 nodes per warp, f32x2 pairs -------------
    __shared__ float2 xs[8][4][136];
    int warp = tid >> 5, lane = tid & 31;
    int ngrp = (N + 7) >> 3;
    int grp = (bid - 128 - PB) * 8 + warp;
    if (grp >= ngrp) return;
    int nbase = grp * 8;
    int o4 = (lane < 4) ? (128 + lane) : lane;

    float attv[8];
#pragma unroll
    for (int nd = 0; nd < 8; nd++) {
        int n = nbase + nd; if (n >= N) n = N - 1;
        float* Xp = reinterpret_cast<float*>(xs[warp][nd >> 1]) + (nd & 1);
#pragma unroll
        for (int j = 0; j < 4; j++)
            Xp[2 * (lane + 32 * j)] = 2.0f * __ldg(invf + (size_t)n * 128 + lane + 32 * j);
        float av = 0.f, dsq = 0.f;
        if (lane < 16) { av = 2.0f * __ldg(evf + (size_t)n * 16 + lane); dsq = av * av; }
        attv[nd] = av;
        float v0 = __shfl_sync(FULLMASK, dsq, 0);
        float v1 = __shfl_sync(FULLMASK, dsq, 1) + __shfl_sync(FULLMASK, dsq, 2)
                 + __shfl_sync(FULLMASK, dsq, 3);
        float v2 = __shfl_sync(FULLMASK, dsq, 4) + __shfl_sync(FULLMASK, dsq, 5)
                 + __shfl_sync(FULLMASK, dsq, 6) + __shfl_sync(FULLMASK, dsq, 7)
                 + __shfl_sync(FULLMASK, dsq, 8);
        float v3 = __shfl_sync(FULLMASK, dsq, 9) + __shfl_sync(FULLMASK, dsq, 10)
                 + __shfl_sync(FULLMASK, dsq, 11) + __shfl_sync(FULLMASK, dsq, 12)
                 + __shfl_sync(FULLMASK, dsq, 13) + __shfl_sync(FULLMASK, dsq, 14)
                 + __shfl_sync(FULLMASK, dsq, 15);
        if (lane == 0) { Xp[2*128] = v0; Xp[2*129] = v1; Xp[2*130] = v2; Xp[2*131] = v3; }
    }
    __syncwarp();

    ull acc[4][5];
    {
        ull d0 = dup2(__ldg(b_int + lane)),      d1 = dup2(__ldg(b_int + 32 + lane));
        ull d2 = dup2(__ldg(b_int + 64 + lane)), d3 = dup2(__ldg(b_int + 96 + lane));
        ull d4 = dup2(__ldg(b_int + o4));
#pragma unroll
        for (int p = 0; p < 4; p++) {
            acc[p][0] = d0; acc[p][1] = d1; acc[p][2] = d2; acc[p][3] = d3; acc[p][4] = d4;
        }
    }
#pragma unroll 2
    for (int i = 0; i < 132; i++) {
        const float* wr = w_int + i * 132;
        ull w0 = dup2(__ldg(wr + lane)),      w1 = dup2(__ldg(wr + 32 + lane));
        ull w2 = dup2(__ldg(wr + 64 + lane)), w3 = dup2(__ldg(wr + 96 + lane));
        ull w4 = dup2(__ldg(wr + o4));
#pragma unroll
        for (int p = 0; p < 4; p++) {
            ull x = reinterpret_cast<const ull*>(xs[warp][p])[i];
            fma2(acc[p][0], w0, x); fma2(acc[p][1], w1, x);
            fma2(acc[p][2], w2, x); fma2(acc[p][3], w3, x);
            fma2(acc[p][4], w4, x);
        }
    }
#pragma unroll
    for (int nd = 0; nd < 8; nd++) {
        int n = nbase + nd;
        if (n >= N) break;
        int p = nd >> 1, s = nd & 1;
        const float* Xp = reinterpret_cast<const float*>(xs[warp][p]) + s;
        float lo, hi, a0, a1, a2, a3, a4;
        unpack2(acc[p][0], lo, hi); a0 = s ? hi : lo;
        unpack2(acc[p][1], lo, hi); a1 = s ? hi : lo;
        unpack2(acc[p][2], lo, hi); a2 = s ? hi : lo;
        unpack2(acc[p][3], lo, hi); a3 = s ? hi : lo;
        unpack2(acc[p][4], lo, hi); a4 = s ? hi : lo;
        out1[(size_t)n * 128 + lane]      = Xp[2 * (lane)]      + a0;
        out1[(size_t)n * 128 + 32 + lane] = Xp[2 * (32 + lane)] + a1;
        out1[(size_t)n * 128 + 64 + lane] = Xp[2 * (64 + lane)] + a2;
        out1[(size_t)n * 128 + 96 + lane] = Xp[2 * (96 + lane)] + a3;
        float c0 = __shfl_sync(FULLMASK, a4, 0), c1 = __shfl_sync(FULLMASK, a4, 1);
        float c2 = __shfl_sync(FULLMASK, a4, 2), c3 = __shfl_sync(FULLMASK, a4, 3);
        if (lane < 16) {
            float bs = (lane == 0) ? c0 : ((lane < 4) ? c1 : ((lane < 9) ? c2 : c3));
            out2[(size_t)n * 16 + lane] = attv[nd] * (1.0f + bs);
        }
    }
}

// ===========================================================================
// Edge kernel (R5-proven config): blockIdx.y = filter, 8 edges per warp pass.
// fw = tab_lerp_fp16(length) + silu(silu(inv4 @ w1 + b1) @ w2 + b2)
// ===========================================================================
__global__ void __launch_bounds__(256) edge_kernel(
    const float* __restrict__ fi_w1, const float* __restrict__ fi_b1,
    const float* __restrict__ fi_w2, const float* __restrict__ fi_b2,
    const float* __restrict__ fe_w1, const float* __restrict__ fe_b1,
    const float* __restrict__ fe_w2, const float* __restrict__ fe_b2,
    float* __restrict__ fwi, float* __restrict__ fwe, int E)
{
    int filt = blockIdx.y;
    const float* we1 = filt ? fe_w1 : fi_w1; const float* be1 = filt ? fe_b1 : fi_b1;
    const float* we2 = filt ? fe_w2 : fi_w2; const float* be2 = filt ? fe_b2 : fi_b2;
    float* outp = filt ? fwe : fwi;
    const __half* tabh = g_htabh[filt];

    __shared__ __align__(16) float s_we2[4096];
    __shared__ __align__(16) float2 s_e1[8][4][32];
    __shared__ __align__(16) float4 s_edv[8][8];
    __shared__ float2 s_m[8][8];

    int tid = threadIdx.x;
    for (int i = tid; i < 4096; i += 256) s_we2[i] = we2[i];
    __syncthreads();

    int warp = tid >> 5, lane = tid & 31;
    float w1l0 = __ldg(we1 + lane),      w1l1 = __ldg(we1 + 32 + lane);
    float w1l2 = __ldg(we1 + 64 + lane), w1l3 = __ldg(we1 + 96 + lane);
    float bl   = __ldg(be1 + lane);
    float4 bb  = __ldg(reinterpret_cast<const float4*>(be2) + lane);
    ull bd0 = dup2(bb.x), bd1 = dup2(bb.y), bd2 = dup2(bb.z), bd3 = dup2(bb.w);
    const float4* wv = reinterpret_cast<const float4*>(s_we2);
    float4* outv = reinterpret_cast<float4*>(outp);

    int gw = blockIdx.x * 8 + warp;
    int nwarps = gridDim.x * 8;

    for (int base = gw * 8; base < E; base += nwarps * 8) {
        if (lane < 8) {
            int e = base + lane; if (e >= E) e = E - 1;
            s_edv[warp][lane] = g_einv[e];
            s_m[warp][lane]   = g_etf[e];
        }
        __syncwarp();

        // layer 1: hidden = lane, edge pairs into float2
#pragma unroll
        for (int p = 0; p < 4; p++) {
            float4 v0 = s_edv[warp][2 * p];
            float4 v1 = s_edv[warp][2 * p + 1];
            float ea = silu_f(fmaf(v0.x, w1l0, fmaf(v0.y, w1l1,
                              fmaf(v0.z, w1l2, fmaf(v0.w, w1l3, bl)))));
            float eb = silu_f(fmaf(v1.x, w1l0, fmaf(v1.y, w1l1,
                              fmaf(v1.z, w1l2, fmaf(v1.w, w1l3, bl)))));
            s_e1[warp][p][lane] = make_float2(ea, eb);
        }
        __syncwarp();

        // layer 2: 32 -> 128, f32x2 over edge pairs, v4 activation loads
        ull acc[4][4];
#pragma unroll
        for (int p = 0; p < 4; p++) { acc[p][0] = bd0; acc[p][1] = bd1; acc[p][2] = bd2; acc[p][3] = bd3; }
        const float4* e1v = reinterpret_cast<const float4*>(s_e1[warp]);
#pragma unroll 2
        for (int k2 = 0; k2 < 16; k2++) {
            float4 wa = wv[(2 * k2) * 32 + lane];
            float4 wb = wv[(2 * k2 + 1) * 32 + lane];
            ull wa0 = dup2(wa.x), wa1 = dup2(wa.y), wa2 = dup2(wa.z), wa3 = dup2(wa.w);
            ull wb0 = dup2(wb.x), wb1 = dup2(wb.y), wb2 = dup2(wb.z), wb3 = dup2(wb.w);
#pragma unroll
            for (int p = 0; p < 4; p++) {
                float4 cc = e1v[p * 16 + k2];
                ull c0 = pack2(cc.x, cc.y);
                ull c1 = pack2(cc.z, cc.w);
                fma2(acc[p][0], wa0, c0); fma2(acc[p][1], wa1, c0);
                fma2(acc[p][2], wa2, c0); fma2(acc[p][3], wa3, c0);
                fma2(acc[p][0], wb0, c1); fma2(acc[p][1], wb1, c1);
                fma2(acc[p][2], wb2, c1); fma2(acc[p][3], wb3, c1);
            }
        }

        // epilogue: silu + fp16 table lerp + store
#pragma unroll
        for (int p = 0; p < 4; p++) {
            float l0, h0, l1, h1, l2, h2, l3, h3;
            unpack2(acc[p][0], l0, h0); unpack2(acc[p][1], l1, h1);
            unpack2(acc[p][2], l2, h2); unpack2(acc[p][3], l3, h3);
#pragma unroll
            for (int hh = 0; hh < 2; hh++) {
                int j = 2 * p + hh;
                int e = base + j;
                if (e < E) {
                    float e0 = hh ? h0 : l0, e1 = hh ? h1 : l1;
                    float e2 = hh ? h2 : l2, e3 = hh ? h3 : l3;
                    float tf = s_m[warp][j].x;
                    int   ti = __float_as_int(s_m[warp][j].y);
                    const uint2* ta = reinterpret_cast<const uint2*>(tabh + (size_t)ti * 128) + lane;
                    uint2 ua = __ldg(ta);
                    uint2 ub = __ldg(ta + 32);
                    float2 a01 = __half22float2(*reinterpret_cast<__half2*>(&ua.x));
                    float2 a23 = __half22float2(*reinterpret_cast<__half2*>(&ua.y));
                    float2 b01 = __half22float2(*reinterpret_cast<__half2*>(&ub.x));
                    float2 b23 = __half22float2(*reinterpret_cast<__half2*>(&ub.y));
                    float4 o;
                    o.x = fmaf(tf, b01.x - a01.x, a01.x) + silu_f(e0);
                    o.y = fmaf(tf, b01.y - a01.y, a01.y) + silu_f(e1);
                    o.z = fmaf(tf, b23.x - a23.x, a23.x) + silu_f(e2);
                    o.w = fmaf(tf, b23.y - a23.y, a23.y) + silu_f(e3);
                    outv[(size_t)e * 32 + lane] = o;
                }
            }
        }
        __syncwarp();
    }
}

// ---------------------------------------------------------------------------
extern "C" void kernel_launch(void* const* d_in, const int* in_sizes, int n_in,
                              void* d_out, int out_size)
{
    const float* invf      = (const float*)d_in[0];
    const float* evf       = (const float*)d_in[1];
    const int*   senders   = (const int*)  d_in[2];
    const int*   receivers = (const int*)  d_in[3];
    const float* lengths   = (const float*)d_in[5];
    const float* fi_rbf_w1 = (const float*)d_in[7];
    const float* fi_rbf_b1 = (const float*)d_in[8];
    const float* fi_rbf_w2 = (const float*)d_in[9];
    const float* fi_rbf_b2 = (const float*)d_in[10];
    const float* fi_ev_w1  = (const float*)d_in[11];
    const float* fi_ev_b1  = (const float*)d_in[12];
    const float* fi_ev_w2  = (const float*)d_in[13];
    const float* fi_ev_b2  = (const float*)d_in[14];
    const float* fe_rbf_w1 = (const float*)d_in[15];
    const float* fe_rbf_b1 = (const float*)d_in[16];
    const float* fe_rbf_w2 = (const float*)d_in[17];
    const float* fe_rbf_b2 = (const float*)d_in[18];
    const float* fe_ev_w1  = (const float*)d_in[19];
    const float* fe_ev_b1  = (const float*)d_in[20];
    const float* fe_ev_w2  = (const float*)d_in[21];
    const float* fe_ev_b2  = (const float*)d_in[22];
    const float* w_int     = (const float*)d_in[23];
    const float* b_int     = (const float*)d_in[24];

    int N = in_sizes[0] / 128;
    int E = in_sizes[5];

    float* out1 = (float*)d_out;
    float* out2 = out1 + (size_t)N * 128;
    float* fwi  = out2 + (size_t)N * 16;
    float* fwe  = fwi  + (size_t)E * 128;

    int PB = (E + 255) / 256;
    int NB = (((N + 7) / 8) + 7) / 8;

    setup_kernel<<<128 + PB + NB, 256>>>(
        invf, evf, senders, receivers, lengths,
        fi_rbf_w1, fi_rbf_b1, fi_rbf_w2, fi_rbf_b2,
        fe_rbf_w1, fe_rbf_b1, fe_rbf_w2, fe_rbf_b2,
        w_int, b_int, out1, out2, N, E, PB);

    edge_kernel<<<dim3(1184, 2), 256>>>(
        fi_ev_w1, fi_ev_b1, fi_ev_w2, fi_ev_b2,
        fe_ev_w1, fe_ev_b1, fe_ev_w2, fe_ev_b2,
        fwi, fwe, E);
}